// round 15
// baseline (speedup 1.0000x reference)
#include <cuda_runtime.h>
#include <cuda_bf16.h>
#include <math.h>
#include <stdint.h>

#define BN    16
#define TTN   1026
#define LENN  1024
#define NTOT  (BN*LENN)

/* ---- per-channel weight fragment blob (bytes) ---- */
#define WIMG_W1H   0
#define WIMG_W1L   16384
#define WIMG_W2H   32768
#define WIMG_W2L   40960
#define WIMG_WWH   49152
#define WIMG_WWL   57344
#define WIMG_SCAL  65536        /* quads: [b1,b1,w1l,w1l]x32, [b2,b2,w3,w3]x32, b3 */
#define WIMG_STRIDE 66816

/* ---- smem layout (bytes): A-hi only + x_t (occ-4 target) ---- */
#define SM_A1H  0               /* 32 KB */
#define SM_XT   32768           /* 128 rows x 4 ch x f32 = 2 KB */
#define SM_TOTAL 34816

__device__ __align__(16) unsigned char g_wimg[64 * (size_t)WIMG_STRIDE];
__device__ __align__(16) uint4 g_a1h[128 * 2048];
__device__ __align__(16) uint4 g_a1l[128 * 2048];
__device__ float g_logpart[NTOT * 64];

/* ================= helpers ================= */
__device__ __forceinline__ uint32_t pkbf(float lo, float hi) {
    uint32_t r;
    asm("cvt.rn.bf16x2.f32 %0, %1, %2;" : "=r"(r) : "f"(hi), "f"(lo));
    return r;
}
__device__ __forceinline__ float bfh(float v) {
    return __bfloat162float(__float2bfloat16_rn(v));
}
__device__ __forceinline__ void mma_bf16(float& d0, float& d1, float& d2, float& d3,
                                         uint32_t a0, uint32_t a1, uint32_t a2, uint32_t a3,
                                         uint32_t b0, uint32_t b1) {
    asm volatile("mma.sync.aligned.m16n8k16.row.col.f32.bf16.bf16.f32 "
        "{%0,%1,%2,%3}, {%4,%5,%6,%7}, {%8,%9}, {%0,%1,%2,%3};"
        : "+f"(d0), "+f"(d1), "+f"(d2), "+f"(d3)
        : "r"(a0), "r"(a1), "r"(a2), "r"(a3), "r"(b0), "r"(b1));
}
__device__ __forceinline__ void cpa16(uint32_t dst, const void* src) {
    asm volatile("cp.async.cg.shared.global [%0], [%1], 16;" :: "r"(dst), "l"(src) : "memory");
}
#define CPA_COMMIT() asm volatile("cp.async.commit_group;" ::: "memory")
#define CPA_WAIT(n)  asm volatile("cp.async.wait_group %0;" :: "n"(n) : "memory")

__host__ __device__ __forceinline__ uint32_t bpair_off(int kt, int nt, int lane) {
    return (uint32_t)(kt * 4 + (nt >> 1)) * 512u + (uint32_t)lane * 16u + (uint32_t)(nt & 1) * 8u;
}

__global__ void noop_kernel() {}

/* ================= prep: X -> split A fragments (128-row tiles) ================= */
__global__ void prep_x_kernel(const float* __restrict__ x)
{
    const int tile = blockIdx.x;                      /* 0..127 */
    const int bb = tile >> 3, t0 = (tile & 7) * 128;
    const int gid = blockIdx.y * 256 + threadIdx.x;   /* 0..2047 */
    const int ft = gid >> 5, lane = gid & 31;
    const int mt = ft >> 3, kt = ft & 7;
    const int row0 = mt * 16 + (lane >> 2);
    const int c0 = kt * 16 + (lane & 3) * 2;

    const float* xb = x + (size_t)(bb * TTN + t0 + row0) * 64;
    float2 p00 = *(const float2*)(xb + c0);
    float2 p10 = *(const float2*)(xb + 8 * 64 + c0);
    float2 p01 = *(const float2*)(xb + c0 + 8);
    float2 p11 = *(const float2*)(xb + 8 * 64 + c0 + 8);

    uint4 hi, lo;
    hi.x = pkbf(p00.x, p00.y); lo.x = pkbf(p00.x - bfh(p00.x), p00.y - bfh(p00.y));
    hi.y = pkbf(p10.x, p10.y); lo.y = pkbf(p10.x - bfh(p10.x), p10.y - bfh(p10.y));
    hi.z = pkbf(p01.x, p01.y); lo.z = pkbf(p01.x - bfh(p01.x), p01.y - bfh(p01.y));
    hi.w = pkbf(p11.x, p11.y); lo.w = pkbf(p11.x - bfh(p11.x), p11.y - bfh(p11.y));
    g_a1h[(size_t)tile * 2048 + gid] = hi;
    g_a1l[(size_t)tile * 2048 + gid] = lo;
}

/* ================= prep: weights -> paired B blobs + scalar quads ================= */
__global__ void prep_w_kernel(const float* __restrict__ W1, const float* __restrict__ b1,
                              const float* __restrict__ W2, const float* __restrict__ b2,
                              const float* __restrict__ W3, const float* __restrict__ b3)
{
    const int l = blockIdx.x, tid = threadIdx.x;
    unsigned char* blob = g_wimg + (size_t)l * WIMG_STRIDE;
    const float* W1c = W1 + (size_t)l * 64 * 129;
    const float* W2c = W2 + (size_t)l * 64 * 64;

    for (int idx = tid; idx < 2048; idx += 256) {
        int ft = idx >> 5, lane = idx & 31;
        int kt = ft >> 3, nt = ft & 7;
        int n0 = nt * 8 + (lane >> 2);
        int k0 = kt * 16 + (lane & 3) * 2;
        const float* wr = W1c + n0 * 129;
        float v0 = wr[k0], v1 = wr[k0 + 1], v2 = wr[k0 + 8], v3 = wr[k0 + 9];
        uint32_t off = bpair_off(kt, nt, lane);
        *(uint2*)(blob + WIMG_W1H + off) = make_uint2(pkbf(v0, v1), pkbf(v2, v3));
        *(uint2*)(blob + WIMG_W1L + off) = make_uint2(
            pkbf(v0 - bfh(v0), v1 - bfh(v1)), pkbf(v2 - bfh(v2), v3 - bfh(v3)));
    }
    for (int idx = tid; idx < 1024; idx += 256) {
        int ft = idx >> 5, lane = idx & 31;
        int kt = ft >> 3, nt = ft & 7;
        int n0 = nt * 8 + (lane >> 2);
        int k0 = kt * 16 + (lane & 3) * 2;
        float v0 = W2c[n0 * 64 + k0],     v1 = W2c[n0 * 64 + k0 + 1];
        float v2 = W2c[n0 * 64 + k0 + 8], v3 = W2c[n0 * 64 + k0 + 9];
        uint32_t off = bpair_off(kt, nt, lane);
        *(uint2*)(blob + WIMG_W2H + off) = make_uint2(pkbf(v0, v1), pkbf(v2, v3));
        *(uint2*)(blob + WIMG_W2L + off) = make_uint2(
            pkbf(v0 - bfh(v0), v1 - bfh(v1)), pkbf(v2 - bfh(v2), v3 - bfh(v3)));
        float u0 = 0.01f * W1c[(k0)     * 129 + 128] * v0;
        float u1 = 0.01f * W1c[(k0 + 1) * 129 + 128] * v1;
        float u2 = 0.01f * W1c[(k0 + 8) * 129 + 128] * v2;
        float u3 = 0.01f * W1c[(k0 + 9) * 129 + 128] * v3;
        *(uint2*)(blob + WIMG_WWH + off) = make_uint2(pkbf(u0, u1), pkbf(u2, u3));
        *(uint2*)(blob + WIMG_WWL + off) = make_uint2(
            pkbf(u0 - bfh(u0), u1 - bfh(u1)), pkbf(u2 - bfh(u2), u3 - bfh(u3)));
    }
    float* sc = (float*)(blob + WIMG_SCAL);
    if (tid < 32) {
        int p = tid;
        sc[p * 4 + 0] = b1[l * 64 + 2 * p];
        sc[p * 4 + 1] = b1[l * 64 + 2 * p + 1];
        sc[p * 4 + 2] = W1c[(2 * p) * 129 + 128];
        sc[p * 4 + 3] = W1c[(2 * p + 1) * 129 + 128];
        sc[128 + p * 4 + 0] = b2[l * 64 + 2 * p];
        sc[128 + p * 4 + 1] = b2[l * 64 + 2 * p + 1];
        sc[128 + p * 4 + 2] = W3[l * 64 + 2 * p];
        sc[128 + p * 4 + 3] = W3[l * 64 + 2 * p + 1];
    }
    if (tid == 0) sc[256] = b3[l];
}

/* ====== main: mt=2 G1, per-mt G2/Gt, A-lo from global, occ 4, rotation ====== */
__global__ __launch_bounds__(128, 4)
void mlp_hmma_kernel(const float* __restrict__ x, float* __restrict__ out_res)
{
    extern __shared__ unsigned char smem[];
    const int tid = threadIdx.x;
    const int w = tid >> 5, lane = tid & 31;
    const int g = lane >> 2, tg = lane & 3;
    const int tile = blockIdx.x, bb = tile >> 3, t0 = (tile & 7) * 128;
    const int l0 = blockIdx.y * 4;
    const uint32_t sbase = (uint32_t)__cvta_generic_to_shared(smem);

    /* x_t staging: 128 rows x 4 ch */
    {
        const float4* src = (const float4*)(x + (size_t)(bb * TTN + t0 + tid + 2) * 64 + l0);
        *(float4*)(smem + SM_XT + tid * 16) = src[0];
    }
    /* A-hi fragments -> smem; A-lo stays in global */
    {
        const uint4* ah = g_a1h + (size_t)tile * 2048;
        for (int i = tid; i < 2048; i += 128)
            cpa16(sbase + SM_A1H + i * 16, ah + i);
        CPA_COMMIT();
        CPA_WAIT(0);
    }
    __syncthreads();

    const uint4* a1hq = (const uint4*)(smem + SM_A1H);
    const uint4* a1lg = g_a1l + (size_t)tile * 2048;   /* global A-lo */

    #pragma unroll 1
    for (int cj = 0; cj < 4; cj++) {
        const int lch = (cj + w) & 3;
        const int l = l0 + lch;
        const unsigned char* wbp = g_wimg + (size_t)l * WIMG_STRIDE;
        const float4* scq = (const float4*)(wbp + WIMG_SCAL);

        /* ---- GEMM1: z1 = X * W1^T, mt=2; passes 0,1 smem A-hi, pass 2 global A-lo ---- */
        float z1[2][8][4];
        #pragma unroll
        for (int mt = 0; mt < 2; mt++)
            #pragma unroll
            for (int nt = 0; nt < 8; nt++)
                #pragma unroll
                for (int e = 0; e < 4; e++) z1[mt][nt][e] = 0.f;

        #pragma unroll 1
        for (int pass = 0; pass < 2; pass++) {
            const uint4* Bq = (const uint4*)(wbp + (pass ? WIMG_W1L : WIMG_W1H));
            #pragma unroll
            for (int kt = 0; kt < 8; kt++) {
                uint4 af0 = a1hq[((w * 2 + 0) * 8 + kt) * 32 + lane];
                uint4 af1 = a1hq[((w * 2 + 1) * 8 + kt) * 32 + lane];
                #pragma unroll
                for (int np = 0; np < 4; np++) {
                    uint4 bq = __ldg(&Bq[(kt * 4 + np) * 32 + lane]);
                    int n0 = np * 2, n1 = np * 2 + 1;
                    mma_bf16(z1[0][n0][0], z1[0][n0][1], z1[0][n0][2], z1[0][n0][3],
                             af0.x, af0.y, af0.z, af0.w, bq.x, bq.y);
                    mma_bf16(z1[1][n0][0], z1[1][n0][1], z1[1][n0][2], z1[1][n0][3],
                             af1.x, af1.y, af1.z, af1.w, bq.x, bq.y);
                    mma_bf16(z1[0][n1][0], z1[0][n1][1], z1[0][n1][2], z1[0][n1][3],
                             af0.x, af0.y, af0.z, af0.w, bq.z, bq.w);
                    mma_bf16(z1[1][n1][0], z1[1][n1][1], z1[1][n1][2], z1[1][n1][3],
                             af1.x, af1.y, af1.z, af1.w, bq.z, bq.w);
                }
            }
        }
        {   /* pass 2: A-lo (global) x W1H */
            const uint4* Bq = (const uint4*)(wbp + WIMG_W1H);
            #pragma unroll
            for (int kt = 0; kt < 8; kt++) {
                uint4 af0 = __ldg(&a1lg[((w * 2 + 0) * 8 + kt) * 32 + lane]);
                uint4 af1 = __ldg(&a1lg[((w * 2 + 1) * 8 + kt) * 32 + lane]);
                #pragma unroll
                for (int np = 0; np < 4; np++) {
                    uint4 bq = __ldg(&Bq[(kt * 4 + np) * 32 + lane]);
                    int n0 = np * 2, n1 = np * 2 + 1;
                    mma_bf16(z1[0][n0][0], z1[0][n0][1], z1[0][n0][2], z1[0][n0][3],
                             af0.x, af0.y, af0.z, af0.w, bq.x, bq.y);
                    mma_bf16(z1[1][n0][0], z1[1][n0][1], z1[1][n0][2], z1[1][n0][3],
                             af1.x, af1.y, af1.z, af1.w, bq.x, bq.y);
                    mma_bf16(z1[0][n1][0], z1[0][n1][1], z1[0][n1][2], z1[0][n1][3],
                             af0.x, af0.y, af0.z, af0.w, bq.z, bq.w);
                    mma_bf16(z1[1][n1][0], z1[1][n1][1], z1[1][n1][2], z1[1][n1][3],
                             af1.x, af1.y, af1.z, af1.w, bq.z, bq.w);
                }
            }
        }

        /* ---- epilogue 1: bias + rank-1, leaky, split (both mts) ---- */
        uint32_t ah[2][4][4], al[2][4][4];
        #pragma unroll
        for (int mt = 0; mt < 2; mt++) {
            int r0 = w * 32 + mt * 16 + g;
            float xtr0 = *(const float*)(smem + SM_XT + r0 * 16 + lch * 4);
            float xtr1 = *(const float*)(smem + SM_XT + (r0 + 8) * 16 + lch * 4);
            #pragma unroll
            for (int kt2 = 0; kt2 < 4; kt2++)
            #pragma unroll
            for (int half = 0; half < 2; half++) {
                int nt = kt2 * 2 + half;
                float4 q = __ldg(&scq[nt * 4 + tg]);   /* b1a,b1b,w1la,w1lb */
                float za = z1[mt][nt][0] + fmaf(xtr0, q.z, q.x);
                float zb = z1[mt][nt][1] + fmaf(xtr0, q.w, q.y);
                float zc = z1[mt][nt][2] + fmaf(xtr1, q.z, q.x);
                float zd = z1[mt][nt][3] + fmaf(xtr1, q.w, q.y);
                float aa = fmaxf(za, 0.01f * za);
                float ab = fmaxf(zb, 0.01f * zb);
                float ac = fmaxf(zc, 0.01f * zc);
                float ad = fmaxf(zd, 0.01f * zd);
                uint32_t p0 = pkbf(aa, ab);
                uint32_t p1 = pkbf(ac, ad);
                ah[mt][kt2][half * 2 + 0] = p0;
                ah[mt][kt2][half * 2 + 1] = p1;
                al[mt][kt2][half * 2 + 0] = pkbf(aa - __uint_as_float(p0 << 16),
                                                 ab - __uint_as_float(p0 & 0xffff0000u));
                al[mt][kt2][half * 2 + 1] = pkbf(ac - __uint_as_float(p1 << 16),
                                                 ad - __uint_as_float(p1 & 0xffff0000u));
            }
        }

        /* ---- per-mt: GEMM2 + out head + GEMM-t + dJ head ---- */
        const float b3v = __ldg(&((const float*)(wbp + WIMG_SCAL))[256]);
        #pragma unroll 1
        for (int mt = 0; mt < 2; mt++) {
            /* GEMM2: z2 = a1 * W2^T (3 passes) */
            float zA[8][4];
            #pragma unroll
            for (int nt = 0; nt < 8; nt++)
                #pragma unroll
                for (int e = 0; e < 4; e++) zA[nt][e] = 0.f;
            #pragma unroll 1
            for (int pass = 0; pass < 3; pass++) {
                const uint32_t* Af = (pass < 2) ? &ah[mt][0][0] : &al[mt][0][0];
                const uint4* Bq = (const uint4*)(wbp + ((pass == 1) ? WIMG_W2L : WIMG_W2H));
                #pragma unroll
                for (int kt = 0; kt < 4; kt++) {
                    #pragma unroll
                    for (int np = 0; np < 4; np++) {
                        uint4 bq = __ldg(&Bq[(kt * 4 + np) * 32 + lane]);
                        int n0 = np * 2, n1 = np * 2 + 1;
                        mma_bf16(zA[n0][0], zA[n0][1], zA[n0][2], zA[n0][3],
                                 Af[kt * 4 + 0], Af[kt * 4 + 1], Af[kt * 4 + 2], Af[kt * 4 + 3],
                                 bq.x, bq.y);
                        mma_bf16(zA[n1][0], zA[n1][1], zA[n1][2], zA[n1][3],
                                 Af[kt * 4 + 0], Af[kt * 4 + 1], Af[kt * 4 + 2], Af[kt * 4 + 3],
                                 bq.z, bq.w);
                    }
                }
            }

            /* out head + z2 sign flags */
            float po0 = 0.f, po1 = 0.f;
            uint32_t z2fl = 0u;
            #pragma unroll
            for (int nt = 0; nt < 8; nt++) {
                float4 q = __ldg(&scq[32 + nt * 4 + tg]);  /* b2a,b2b,w3a,w3b */
                #pragma unroll
                for (int e = 0; e < 4; e++) {
                    float b2v = (e & 1) ? q.y : q.x;
                    float w3v = (e & 1) ? q.w : q.z;
                    float z2 = zA[nt][e] + b2v;
                    float a2 = fmaxf(z2, 0.01f * z2);
                    if (e >> 1) po1 = fmaf(a2, w3v, po1);
                    else        po0 = fmaf(a2, w3v, po0);
                    z2fl |= (z2 > 0.f ? 1u : 0u) << (nt * 4 + e);
                }
            }

            /* GEMM-t: c' from ah sign bits, 2 passes */
            float tA[8][4];
            #pragma unroll
            for (int nt = 0; nt < 8; nt++)
                #pragma unroll
                for (int e = 0; e < 4; e++) tA[nt][e] = 0.f;
            #pragma unroll 1
            for (int pass = 0; pass < 2; pass++) {
                const uint4* Bq = (const uint4*)(wbp + (pass ? WIMG_WWL : WIMG_WWH));
                #pragma unroll
                for (int kt = 0; kt < 4; kt++) {
                    uint32_t cf0 = 0x42C842C8u ^ (((ah[mt][kt][0] & 0x80008000u) >> 15) * 0x7D48u);
                    uint32_t cf1 = 0x42C842C8u ^ (((ah[mt][kt][1] & 0x80008000u) >> 15) * 0x7D48u);
                    uint32_t cf2 = 0x42C842C8u ^ (((ah[mt][kt][2] & 0x80008000u) >> 15) * 0x7D48u);
                    uint32_t cf3 = 0x42C842C8u ^ (((ah[mt][kt][3] & 0x80008000u) >> 15) * 0x7D48u);
                    #pragma unroll
                    for (int np = 0; np < 4; np++) {
                        uint4 bq = __ldg(&Bq[(kt * 4 + np) * 32 + lane]);
                        int n0 = np * 2, n1 = np * 2 + 1;
                        mma_bf16(tA[n0][0], tA[n0][1], tA[n0][2], tA[n0][3],
                                 cf0, cf1, cf2, cf3, bq.x, bq.y);
                        mma_bf16(tA[n1][0], tA[n1][1], tA[n1][2], tA[n1][3],
                                 cf0, cf1, cf2, cf3, bq.z, bq.w);
                    }
                }
            }

            /* dJ head; quad reduce; write */
            float pd0 = 0.f, pd1 = 0.f;
            #pragma unroll
            for (int nt = 0; nt < 8; nt++) {
                float4 q = __ldg(&scq[32 + nt * 4 + tg]);
                #pragma unroll
                for (int e = 0; e < 4; e++) {
                    float w3v = (e & 1) ? q.w : q.z;
                    float c = ((z2fl >> (nt * 4 + e)) & 1u) ? 1.0f : 0.01f;
                    if (e >> 1) pd1 = fmaf(c * tA[nt][e], w3v, pd1);
                    else        pd0 = fmaf(c * tA[nt][e], w3v, pd0);
                }
            }
            float po[2] = {po0, po1}, pd[2] = {pd0, pd1};
            #pragma unroll
            for (int ri = 0; ri < 2; ri++) {
                float o = po[ri], dd = pd[ri];
                o += __shfl_xor_sync(0xffffffffu, o, 1);
                o += __shfl_xor_sync(0xffffffffu, o, 2);
                dd += __shfl_xor_sync(0xffffffffu, dd, 1);
                dd += __shfl_xor_sync(0xffffffffu, dd, 2);
                if (tg == 0) {
                    int row = w * 32 + mt * 16 + g + ri * 8;
                    size_t n = (size_t)bb * LENN + t0 + row;
                    out_res[n * 64 + l]   = o + b3v;
                    g_logpart[n * 64 + l] = __logf(fabsf(dd));
                }
            }
        }
    }
}

/* deterministic per-sample sum over 64 channels */
__global__ void reduce_log_kernel(float* __restrict__ out_log)
{
    int n = blockIdx.x * blockDim.x + threadIdx.x;
    const float4* p = reinterpret_cast<const float4*>(g_logpart + (size_t)n * 64);
    float s = 0.f;
    #pragma unroll
    for (int i = 0; i < 16; i++) {
        float4 v = p[i];
        s += (v.x + v.y) + (v.z + v.w);
    }
    out_log[n] = s;
}

extern "C" void kernel_launch(void* const* d_in, const int* in_sizes, int n_in,
                              void* d_out, int out_size)
{
    const float* x  = (const float*)d_in[0];
    const float* W1 = (const float*)d_in[1];
    const float* b1 = (const float*)d_in[2];
    const float* W2 = (const float*)d_in[3];
    const float* b2 = (const float*)d_in[4];
    const float* W3 = (const float*)d_in[5];
    const float* b3 = (const float*)d_in[6];
    float* out = (float*)d_out;

    noop_kernel<<<1, 32>>>();
    prep_x_kernel<<<dim3(128, 8), 256>>>(x);
    prep_w_kernel<<<64, 256>>>(W1, b1, W2, b2, W3, b3);

    cudaFuncSetAttribute(mlp_hmma_kernel,
                         cudaFuncAttributeMaxDynamicSharedMemorySize, SM_TOTAL);
    mlp_hmma_kernel<<<dim3(128, 16), 128, SM_TOTAL>>>(x, out);
    reduce_log_kernel<<<NTOT / 256, 256>>>(out + (size_t)NTOT * 64);
}

// round 16
// speedup vs baseline: 1.1155x; 1.1155x over previous
#include <cuda_runtime.h>
#include <cuda_bf16.h>
#include <math.h>
#include <stdint.h>

#define BN    16
#define TTN   1026
#define LENN  1024
#define NTOT  (BN*LENN)

/* ---- per-channel weight fragment blob (bytes) ---- */
#define WIMG_W1H   0
#define WIMG_W1L   16384
#define WIMG_W2H   32768
#define WIMG_W2L   40960
#define WIMG_WWH   49152
#define WIMG_WWL   57344
#define WIMG_SCAL  65536        /* quads: [b1,b1,w1l,w1l]x32, [b2,b2,w3,w3]x32, b3 */
#define WIMG_STRIDE 66816

/* ---- smem layout (bytes): 128-row tile, 2-channel group ---- */
#define SM_A1H  0               /* 32 KB */
#define SM_A1L  32768           /* 32 KB */
#define SM_XT   65536           /* 128 rows x 2 ch x f32 = 1 KB */
#define SM_TOTAL 66560

__device__ __align__(16) unsigned char g_wimg[64 * (size_t)WIMG_STRIDE];
__device__ __align__(16) uint4 g_a1h[128 * 2048];
__device__ __align__(16) uint4 g_a1l[128 * 2048];
__device__ float g_logpart[NTOT * 64];

/* ================= helpers ================= */
__device__ __forceinline__ uint32_t pkbf(float lo, float hi) {
    uint32_t r;
    asm("cvt.rn.bf16x2.f32 %0, %1, %2;" : "=r"(r) : "f"(hi), "f"(lo));
    return r;
}
__device__ __forceinline__ float bfh(float v) {
    return __bfloat162float(__float2bfloat16_rn(v));
}
__device__ __forceinline__ void mma_bf16(float& d0, float& d1, float& d2, float& d3,
                                         uint32_t a0, uint32_t a1, uint32_t a2, uint32_t a3,
                                         uint32_t b0, uint32_t b1) {
    asm volatile("mma.sync.aligned.m16n8k16.row.col.f32.bf16.bf16.f32 "
        "{%0,%1,%2,%3}, {%4,%5,%6,%7}, {%8,%9}, {%0,%1,%2,%3};"
        : "+f"(d0), "+f"(d1), "+f"(d2), "+f"(d3)
        : "r"(a0), "r"(a1), "r"(a2), "r"(a3), "r"(b0), "r"(b1));
}
__device__ __forceinline__ void cpa16(uint32_t dst, const void* src) {
    asm volatile("cp.async.cg.shared.global [%0], [%1], 16;" :: "r"(dst), "l"(src) : "memory");
}
#define CPA_COMMIT() asm volatile("cp.async.commit_group;" ::: "memory")
#define CPA_WAIT(n)  asm volatile("cp.async.wait_group %0;" :: "n"(n) : "memory")

__host__ __device__ __forceinline__ uint32_t bpair_off(int kt, int nt, int lane) {
    return (uint32_t)(kt * 4 + (nt >> 1)) * 512u + (uint32_t)lane * 16u + (uint32_t)(nt & 1) * 8u;
}

__global__ void noop_kernel() {}

/* ================= prep: X -> split A fragments (128-row tiles) ================= */
__global__ void prep_x_kernel(const float* __restrict__ x)
{
    const int tile = blockIdx.x;                      /* 0..127 */
    const int bb = tile >> 3, t0 = (tile & 7) * 128;
    const int gid = blockIdx.y * 256 + threadIdx.x;   /* 0..2047 */
    const int ft = gid >> 5, lane = gid & 31;
    const int mt = ft >> 3, kt = ft & 7;
    const int row0 = mt * 16 + (lane >> 2);
    const int c0 = kt * 16 + (lane & 3) * 2;

    const float* xb = x + (size_t)(bb * TTN + t0 + row0) * 64;
    float2 p00 = *(const float2*)(xb + c0);
    float2 p10 = *(const float2*)(xb + 8 * 64 + c0);
    float2 p01 = *(const float2*)(xb + c0 + 8);
    float2 p11 = *(const float2*)(xb + 8 * 64 + c0 + 8);

    uint4 hi, lo;
    hi.x = pkbf(p00.x, p00.y); lo.x = pkbf(p00.x - bfh(p00.x), p00.y - bfh(p00.y));
    hi.y = pkbf(p10.x, p10.y); lo.y = pkbf(p10.x - bfh(p10.x), p10.y - bfh(p10.y));
    hi.z = pkbf(p01.x, p01.y); lo.z = pkbf(p01.x - bfh(p01.x), p01.y - bfh(p01.y));
    hi.w = pkbf(p11.x, p11.y); lo.w = pkbf(p11.x - bfh(p11.x), p11.y - bfh(p11.y));
    g_a1h[(size_t)tile * 2048 + gid] = hi;
    g_a1l[(size_t)tile * 2048 + gid] = lo;
}

/* ================= prep: weights -> paired B blobs + scalar quads ================= */
__global__ void prep_w_kernel(const float* __restrict__ W1, const float* __restrict__ b1,
                              const float* __restrict__ W2, const float* __restrict__ b2,
                              const float* __restrict__ W3, const float* __restrict__ b3)
{
    const int l = blockIdx.x, tid = threadIdx.x;
    unsigned char* blob = g_wimg + (size_t)l * WIMG_STRIDE;
    const float* W1c = W1 + (size_t)l * 64 * 129;
    const float* W2c = W2 + (size_t)l * 64 * 64;

    for (int idx = tid; idx < 2048; idx += 256) {
        int ft = idx >> 5, lane = idx & 31;
        int kt = ft >> 3, nt = ft & 7;
        int n0 = nt * 8 + (lane >> 2);
        int k0 = kt * 16 + (lane & 3) * 2;
        const float* wr = W1c + n0 * 129;
        float v0 = wr[k0], v1 = wr[k0 + 1], v2 = wr[k0 + 8], v3 = wr[k0 + 9];
        uint32_t off = bpair_off(kt, nt, lane);
        *(uint2*)(blob + WIMG_W1H + off) = make_uint2(pkbf(v0, v1), pkbf(v2, v3));
        *(uint2*)(blob + WIMG_W1L + off) = make_uint2(
            pkbf(v0 - bfh(v0), v1 - bfh(v1)), pkbf(v2 - bfh(v2), v3 - bfh(v3)));
    }
    for (int idx = tid; idx < 1024; idx += 256) {
        int ft = idx >> 5, lane = idx & 31;
        int kt = ft >> 3, nt = ft & 7;
        int n0 = nt * 8 + (lane >> 2);
        int k0 = kt * 16 + (lane & 3) * 2;
        float v0 = W2c[n0 * 64 + k0],     v1 = W2c[n0 * 64 + k0 + 1];
        float v2 = W2c[n0 * 64 + k0 + 8], v3 = W2c[n0 * 64 + k0 + 9];
        uint32_t off = bpair_off(kt, nt, lane);
        *(uint2*)(blob + WIMG_W2H + off) = make_uint2(pkbf(v0, v1), pkbf(v2, v3));
        *(uint2*)(blob + WIMG_W2L + off) = make_uint2(
            pkbf(v0 - bfh(v0), v1 - bfh(v1)), pkbf(v2 - bfh(v2), v3 - bfh(v3)));
        float u0 = 0.01f * W1c[(k0)     * 129 + 128] * v0;
        float u1 = 0.01f * W1c[(k0 + 1) * 129 + 128] * v1;
        float u2 = 0.01f * W1c[(k0 + 8) * 129 + 128] * v2;
        float u3 = 0.01f * W1c[(k0 + 9) * 129 + 128] * v3;
        *(uint2*)(blob + WIMG_WWH + off) = make_uint2(pkbf(u0, u1), pkbf(u2, u3));
        *(uint2*)(blob + WIMG_WWL + off) = make_uint2(
            pkbf(u0 - bfh(u0), u1 - bfh(u1)), pkbf(u2 - bfh(u2), u3 - bfh(u3)));
    }
    float* sc = (float*)(blob + WIMG_SCAL);
    if (tid < 32) {
        int p = tid;
        sc[p * 4 + 0] = b1[l * 64 + 2 * p];
        sc[p * 4 + 1] = b1[l * 64 + 2 * p + 1];
        sc[p * 4 + 2] = W1c[(2 * p) * 129 + 128];
        sc[p * 4 + 3] = W1c[(2 * p + 1) * 129 + 128];
        sc[128 + p * 4 + 0] = b2[l * 64 + 2 * p];
        sc[128 + p * 4 + 1] = b2[l * 64 + 2 * p + 1];
        sc[128 + p * 4 + 2] = W3[l * 64 + 2 * p];
        sc[128 + p * 4 + 3] = W3[l * 64 + 2 * p + 1];
    }
    if (tid == 0) sc[256] = b3[l];
}

/* ====== main HMMA kernel: R14 body, 2-channel groups (finer tail) ====== */
__global__ __launch_bounds__(128, 3)
void mlp_hmma_kernel(const float* __restrict__ x, float* __restrict__ out_res)
{
    extern __shared__ unsigned char smem[];
    const int tid = threadIdx.x;
    const int w = tid >> 5, lane = tid & 31;
    const int g = lane >> 2, tg = lane & 3;
    const int tile = blockIdx.x, bb = tile >> 3, t0 = (tile & 7) * 128;
    const int l0 = blockIdx.y * 2;
    const uint32_t sbase = (uint32_t)__cvta_generic_to_shared(smem);

    /* x_t staging: 128 rows x 2 ch */
    {
        const float2* src = (const float2*)(x + (size_t)(bb * TTN + t0 + tid + 2) * 64 + l0);
        *(float2*)(smem + SM_XT + tid * 8) = src[0];
    }
    /* A fragments -> smem */
    {
        const uint4* ah = g_a1h + (size_t)tile * 2048;
        const uint4* al = g_a1l + (size_t)tile * 2048;
        for (int i = tid; i < 2048; i += 128) {
            cpa16(sbase + SM_A1H + i * 16, ah + i);
            cpa16(sbase + SM_A1L + i * 16, al + i);
        }
        CPA_COMMIT();
        CPA_WAIT(0);
    }
    __syncthreads();

    const uint4* a1hq = (const uint4*)(smem + SM_A1H);
    const uint4* a1lq = (const uint4*)(smem + SM_A1L);

    #pragma unroll 1
    for (int cj = 0; cj < 2; cj++) {
        /* phase decorrelation: per-warp rotated channel order (2 phases) */
        const int lch = (cj + w) & 1;
        const int l = l0 + lch;
        const unsigned char* wbp = g_wimg + (size_t)l * WIMG_STRIDE;
        const float4* scq = (const float4*)(wbp + WIMG_SCAL);

        /* ---- GEMM1: z1 = X * W1^T (3 split passes), mt=2 ---- */
        float z1[2][8][4];
        #pragma unroll
        for (int mt = 0; mt < 2; mt++)
            #pragma unroll
            for (int nt = 0; nt < 8; nt++)
                #pragma unroll
                for (int e = 0; e < 4; e++) z1[mt][nt][e] = 0.f;

        #pragma unroll 1
        for (int pass = 0; pass < 3; pass++) {
            const uint4* Aq = (pass < 2) ? a1hq : a1lq;
            const uint4* Bq = (const uint4*)(wbp + ((pass == 1) ? WIMG_W1L : WIMG_W1H));
            #pragma unroll
            for (int kt = 0; kt < 8; kt++) {
                uint4 af0 = Aq[((w * 2 + 0) * 8 + kt) * 32 + lane];
                uint4 af1 = Aq[((w * 2 + 1) * 8 + kt) * 32 + lane];
                #pragma unroll
                for (int np = 0; np < 4; np++) {
                    uint4 bq = __ldg(&Bq[(kt * 4 + np) * 32 + lane]);
                    int n0 = np * 2, n1 = np * 2 + 1;
                    mma_bf16(z1[0][n0][0], z1[0][n0][1], z1[0][n0][2], z1[0][n0][3],
                             af0.x, af0.y, af0.z, af0.w, bq.x, bq.y);
                    mma_bf16(z1[1][n0][0], z1[1][n0][1], z1[1][n0][2], z1[1][n0][3],
                             af1.x, af1.y, af1.z, af1.w, bq.x, bq.y);
                    mma_bf16(z1[0][n1][0], z1[0][n1][1], z1[0][n1][2], z1[0][n1][3],
                             af0.x, af0.y, af0.z, af0.w, bq.z, bq.w);
                    mma_bf16(z1[1][n1][0], z1[1][n1][1], z1[1][n1][2], z1[1][n1][3],
                             af1.x, af1.y, af1.z, af1.w, bq.z, bq.w);
                }
            }
        }

        /* ---- epilogue 1: bias + rank-1, leaky, split (both mts) ---- */
        uint32_t ah[2][4][4], al[2][4][4];
        {
            #pragma unroll
            for (int mt = 0; mt < 2; mt++) {
                int r0 = w * 32 + mt * 16 + g;
                float xtr0 = *(const float*)(smem + SM_XT + r0 * 8 + lch * 4);
                float xtr1 = *(const float*)(smem + SM_XT + (r0 + 8) * 8 + lch * 4);
                #pragma unroll
                for (int kt2 = 0; kt2 < 4; kt2++)
                #pragma unroll
                for (int half = 0; half < 2; half++) {
                    int nt = kt2 * 2 + half;
                    float4 q = __ldg(&scq[nt * 4 + tg]);   /* b1a,b1b,w1la,w1lb */
                    float za = z1[mt][nt][0] + fmaf(xtr0, q.z, q.x);
                    float zb = z1[mt][nt][1] + fmaf(xtr0, q.w, q.y);
                    float zc = z1[mt][nt][2] + fmaf(xtr1, q.z, q.x);
                    float zd = z1[mt][nt][3] + fmaf(xtr1, q.w, q.y);
                    float aa = fmaxf(za, 0.01f * za);
                    float ab = fmaxf(zb, 0.01f * zb);
                    float ac = fmaxf(zc, 0.01f * zc);
                    float ad = fmaxf(zd, 0.01f * zd);
                    uint32_t p0 = pkbf(aa, ab);
                    uint32_t p1 = pkbf(ac, ad);
                    ah[mt][kt2][half * 2 + 0] = p0;
                    ah[mt][kt2][half * 2 + 1] = p1;
                    al[mt][kt2][half * 2 + 0] = pkbf(aa - __uint_as_float(p0 << 16),
                                                     ab - __uint_as_float(p0 & 0xffff0000u));
                    al[mt][kt2][half * 2 + 1] = pkbf(ac - __uint_as_float(p1 << 16),
                                                     ad - __uint_as_float(p1 & 0xffff0000u));
                }
            }
        }

        /* ---- GEMM2: z2 = a1 * W2^T (3 passes), mt=2 shared B ---- */
        float zA[2][8][4];
        #pragma unroll
        for (int mt = 0; mt < 2; mt++)
            #pragma unroll
            for (int nt = 0; nt < 8; nt++)
                #pragma unroll
                for (int e = 0; e < 4; e++) zA[mt][nt][e] = 0.f;
        #pragma unroll 1
        for (int pass = 0; pass < 3; pass++) {
            const uint32_t (*Af)[4][4] = (pass < 2) ? ah : al;
            const uint4* Bq = (const uint4*)(wbp + ((pass == 1) ? WIMG_W2L : WIMG_W2H));
            #pragma unroll
            for (int kt = 0; kt < 4; kt++) {
                #pragma unroll
                for (int np = 0; np < 4; np++) {
                    uint4 bq = __ldg(&Bq[(kt * 4 + np) * 32 + lane]);
                    int n0 = np * 2, n1 = np * 2 + 1;
                    mma_bf16(zA[0][n0][0], zA[0][n0][1], zA[0][n0][2], zA[0][n0][3],
                             Af[0][kt][0], Af[0][kt][1], Af[0][kt][2], Af[0][kt][3], bq.x, bq.y);
                    mma_bf16(zA[1][n0][0], zA[1][n0][1], zA[1][n0][2], zA[1][n0][3],
                             Af[1][kt][0], Af[1][kt][1], Af[1][kt][2], Af[1][kt][3], bq.x, bq.y);
                    mma_bf16(zA[0][n1][0], zA[0][n1][1], zA[0][n1][2], zA[0][n1][3],
                             Af[0][kt][0], Af[0][kt][1], Af[0][kt][2], Af[0][kt][3], bq.z, bq.w);
                    mma_bf16(zA[1][n1][0], zA[1][n1][1], zA[1][n1][2], zA[1][n1][3],
                             Af[1][kt][0], Af[1][kt][1], Af[1][kt][2], Af[1][kt][3], bq.z, bq.w);
                }
            }
        }

        /* ---- epilogue 2a: out head; z2 sign flags; free zA ---- */
        float po[2][2] = {{0.f, 0.f}, {0.f, 0.f}};
        uint32_t z2fl[2] = {0u, 0u};
        #pragma unroll
        for (int mt = 0; mt < 2; mt++)
        #pragma unroll
        for (int nt = 0; nt < 8; nt++) {
            float4 q = __ldg(&scq[32 + nt * 4 + tg]);  /* b2a,b2b,w3a,w3b */
            #pragma unroll
            for (int e = 0; e < 4; e++) {
                float b2v = (e & 1) ? q.y : q.x;
                float w3v = (e & 1) ? q.w : q.z;
                float z2 = zA[mt][nt][e] + b2v;
                float a2 = fmaxf(z2, 0.01f * z2);
                po[mt][e >> 1] = fmaf(a2, w3v, po[mt][e >> 1]);
                z2fl[mt] |= (z2 > 0.f ? 1u : 0u) << (nt * 4 + e);
            }
        }

        /* ---- GEMM-t: c' rebuilt per-kt from ah sign bits (2 passes) ---- */
        float tA[2][8][4];
        #pragma unroll
        for (int mt = 0; mt < 2; mt++)
            #pragma unroll
            for (int nt = 0; nt < 8; nt++)
                #pragma unroll
                for (int e = 0; e < 4; e++) tA[mt][nt][e] = 0.f;
        #pragma unroll 1
        for (int pass = 0; pass < 2; pass++) {
            const uint4* Bq = (const uint4*)(wbp + (pass ? WIMG_WWL : WIMG_WWH));
            #pragma unroll
            for (int kt = 0; kt < 4; kt++) {
                uint32_t cf0[4], cf1[4];
                #pragma unroll
                for (int j = 0; j < 4; j++) {
                    uint32_t p0 = ah[0][kt][j];
                    uint32_t p1 = ah[1][kt][j];
                    cf0[j] = 0x42C842C8u ^ (((p0 & 0x80008000u) >> 15) * 0x7D48u);
                    cf1[j] = 0x42C842C8u ^ (((p1 & 0x80008000u) >> 15) * 0x7D48u);
                }
                #pragma unroll
                for (int np = 0; np < 4; np++) {
                    uint4 bq = __ldg(&Bq[(kt * 4 + np) * 32 + lane]);
                    int n0 = np * 2, n1 = np * 2 + 1;
                    mma_bf16(tA[0][n0][0], tA[0][n0][1], tA[0][n0][2], tA[0][n0][3],
                             cf0[0], cf0[1], cf0[2], cf0[3], bq.x, bq.y);
                    mma_bf16(tA[1][n0][0], tA[1][n0][1], tA[1][n0][2], tA[1][n0][3],
                             cf1[0], cf1[1], cf1[2], cf1[3], bq.x, bq.y);
                    mma_bf16(tA[0][n1][0], tA[0][n1][1], tA[0][n1][2], tA[0][n1][3],
                             cf0[0], cf0[1], cf0[2], cf0[3], bq.z, bq.w);
                    mma_bf16(tA[1][n1][0], tA[1][n1][1], tA[1][n1][2], tA[1][n1][3],
                             cf1[0], cf1[1], cf1[2], cf1[3], bq.z, bq.w);
                }
            }
        }

        /* ---- epilogue 2b: dJ head; quad reduce; write (both mts) ---- */
        {
            const float b3v = __ldg(&((const float*)(wbp + WIMG_SCAL))[256]);
            float pd[2][2] = {{0.f, 0.f}, {0.f, 0.f}};
            #pragma unroll
            for (int mt = 0; mt < 2; mt++)
            #pragma unroll
            for (int nt = 0; nt < 8; nt++) {
                float4 q = __ldg(&scq[32 + nt * 4 + tg]);
                #pragma unroll
                for (int e = 0; e < 4; e++) {
                    float w3v = (e & 1) ? q.w : q.z;
                    float c = ((z2fl[mt] >> (nt * 4 + e)) & 1u) ? 1.0f : 0.01f;
                    pd[mt][e >> 1] = fmaf(c * tA[mt][nt][e], w3v, pd[mt][e >> 1]);
                }
            }
            #pragma unroll
            for (int mt = 0; mt < 2; mt++)
            #pragma unroll
            for (int ri = 0; ri < 2; ri++) {
                float o = po[mt][ri], dd = pd[mt][ri];
                o += __shfl_xor_sync(0xffffffffu, o, 1);
                o += __shfl_xor_sync(0xffffffffu, o, 2);
                dd += __shfl_xor_sync(0xffffffffu, dd, 1);
                dd += __shfl_xor_sync(0xffffffffu, dd, 2);
                if (tg == 0) {
                    int row = w * 32 + mt * 16 + g + ri * 8;
                    size_t n = (size_t)bb * LENN + t0 + row;
                    out_res[n * 64 + l]   = o + b3v;
                    g_logpart[n * 64 + l] = __logf(fabsf(dd));
                }
            }
        }
    }
}

/* deterministic per-sample sum over 64 channels */
__global__ void reduce_log_kernel(float* __restrict__ out_log)
{
    int n = blockIdx.x * blockDim.x + threadIdx.x;
    const float4* p = reinterpret_cast<const float4*>(g_logpart + (size_t)n * 64);
    float s = 0.f;
    #pragma unroll
    for (int i = 0; i < 16; i++) {
        float4 v = p[i];
        s += (v.x + v.y) + (v.z + v.w);
    }
    out_log[n] = s;
}

extern "C" void kernel_launch(void* const* d_in, const int* in_sizes, int n_in,
                              void* d_out, int out_size)
{
    const float* x  = (const float*)d_in[0];
    const float* W1 = (const float*)d_in[1];
    const float* b1 = (const float*)d_in[2];
    const float* W2 = (const float*)d_in[3];
    const float* b2 = (const float*)d_in[4];
    const float* W3 = (const float*)d_in[5];
    const float* b3 = (const float*)d_in[6];
    float* out = (float*)d_out;

    noop_kernel<<<1, 32>>>();
    prep_x_kernel<<<dim3(128, 8), 256>>>(x);
    prep_w_kernel<<<64, 256>>>(W1, b1, W2, b2, W3, b3);

    cudaFuncSetAttribute(mlp_hmma_kernel,
                         cudaFuncAttributeMaxDynamicSharedMemorySize, SM_TOTAL);
    mlp_hmma_kernel<<<dim3(128, 32), 128, SM_TOTAL>>>(x, out);
    reduce_log_kernel<<<NTOT / 256, 256>>>(out + (size_t)NTOT * 64);
}